// round 17
// baseline (speedup 1.0000x reference)
#include <cuda_runtime.h>
#include <stdint.h>

// Per-node scalar weight accumulator. Zero-initialized at module load;
// phase 2 consumes and resets -> every invocation/replay starts zeroed.
#define MAX_NODES 100000
__device__ float g_S[MAX_NODES];

// Grid barrier state (epoch-based, self-resetting, replay-safe).
__device__ unsigned g_arrive = 0;
__device__ unsigned g_release = 0;

#define NBLOCKS 296   // 2 CTAs/SM x 148 SMs -> co-resident, barrier-safe
#define NTHREADS 512  // nthreads = 151552, multiple of 8

__global__ void __launch_bounds__(NTHREADS, 2) fused_kernel(
    const int* __restrict__ target, const float* __restrict__ W, int E,
    const float4* __restrict__ x4, float4* __restrict__ out4, int n_vec4)
{
    const int tid = threadIdx.x;
    const int gthread = blockIdx.x * blockDim.x + tid;
    const int nthreads = gridDim.x * blockDim.x;

    // ---------- Phase 1: S[target[e]] += W[e], 8 edges per chunk ----------
    const int nchunks = (E + 7) / 8;
    for (int c = gthread; c < nchunks; c += nthreads) {
        int e = c * 8;
        if (e + 7 < E) {
            int4   ta = *reinterpret_cast<const int4*>(target + e);
            int4   tb = *reinterpret_cast<const int4*>(target + e + 4);
            float4 wa = *reinterpret_cast<const float4*>(W + e);
            float4 wb = *reinterpret_cast<const float4*>(W + e + 4);
            int idx[8] = {ta.x, ta.y, ta.z, ta.w, tb.x, tb.y, tb.z, tb.w};
            float w[8] = {wa.x, wa.y, wa.z, wa.w, wb.x, wb.y, wb.z, wb.w};
            #pragma unroll
            for (int k = 0; k < 8; k++) {
                if ((unsigned)idx[k] < (unsigned)MAX_NODES)
                    atomicAdd(&g_S[idx[k]], w[k]);
            }
        } else {
            for (; e < E; e++) {
                int t = target[e];
                if ((unsigned)t < (unsigned)MAX_NODES)
                    atomicAdd(&g_S[t], W[e]);
            }
        }
    }

    // ---------- Grid barrier (all CTAs co-resident by construction) ----------
    __syncthreads();
    if (tid == 0) {
        unsigned epoch = *(volatile unsigned*)&g_release;  // read BEFORE arriving
        __threadfence();  // publish this block's atomics
        if (atomicAdd(&g_arrive, 1) == (unsigned)gridDim.x - 1) {
            g_arrive = 0;                 // reset for next replay
            __threadfence();
            atomicAdd(&g_release, 1);     // advance epoch -> release
        } else {
            while (*(volatile unsigned*)&g_release == epoch) { }
        }
    }
    __syncthreads();
    __threadfence();

    // ---------- Phase 2: out[v] = x[v] * S[v>>3]; S reset (COALESCED) ----------
    // Grid-stride, consecutive lanes -> consecutive float4s (no wavefront
    // inflation). nthreads % 8 == 0, so one node's 8 vec4s sit in 8
    // consecutive lanes of ONE warp at one iteration: __syncwarp() orders
    // the 8 g_S reads before the single lane's reset store.
    for (int v = gthread; v < n_vec4; v += nthreads) {
        float s = g_S[v >> 3];
        float4 val = x4[v];
        __syncwarp();
        if ((v & 7) == 0) g_S[v >> 3] = 0.0f;
        val.x *= s; val.y *= s; val.z *= s; val.w *= s;
        out4[v] = val;
    }
}

extern "C" void kernel_launch(void* const* d_in, const int* in_sizes, int n_in,
                              void* d_out, int out_size) {
    const int*   edge_index = (const int*)d_in[0];    // [2, E] int32, row-major
    const float* x          = (const float*)d_in[1];  // [N, 32] float32
    const float* W          = (const float*)d_in[2];  // [E] float32

    int E = in_sizes[2];
    int n_vec4 = out_size / 4;               // [N,32] floats -> N*8 float4
    const int* target = edge_index + E;      // row 1 (targets)

    fused_kernel<<<NBLOCKS, NTHREADS>>>(target, W, E,
                                        (const float4*)x, (float4*)d_out, n_vec4);
}